// round 6
// baseline (speedup 1.0000x reference)
#include <cuda_runtime.h>
#include <cuda_bf16.h>
#include <cstdint>

#define NPTS   8192
#define CH     32
#define TILE   256
#define MT     32                      // NPTS / TILE
#define NTILES 528                     // MT*(MT+1)/2 upper-triangle tile pairs
#define NPREP  128                     // prep blocks (8192 / 64)
#define PQ     12                      // padded row stride in b32 words (48B; 32B used)

// ---------------- device scratch (no allocations allowed) -------------------
__device__ float    g_sq[NPTS];
__device__ uint32_t g_xq8[NPTS * 8];      // [n][8] words: 32 int8 channels per point
__device__ float    g_partial[NTILES];
__device__ float    g_diagpart[NPREP];

// ---------------------------------------------------------------------------
// Kernel A (prep): per-point sq (non-FMA tree) + sequential-FMA self-dot ->
// diagonal loss with the reference's rounding-noise structure (bit-identical
// per-point arithmetic to the passing R2/R4/R5 pipeline), plus int8 quantize
// (q = rint(16*x)) staged through smem for coalesced stores.
// ---------------------------------------------------------------------------
__global__ __launch_bounds__(64) void prep_kernel(const float* __restrict__ x) {
    __shared__ uint32_t s8[64 * 8];     // staged int8 rows
    __shared__ float    red[64];

    int tid = threadIdx.x;
    int n = blockIdx.x * 64 + tid;

    float v[CH];
#pragma unroll
    for (int c = 0; c < CH; ++c) v[c] = x[c * NPTS + n];

    // sq: non-FMA rounded products, 4-accumulator tree (XLA-reduce flavor)
    float a0 = 0.f, a1 = 0.f, a2 = 0.f, a3 = 0.f;
#pragma unroll
    for (int c = 0; c < CH; c += 4) {
        a0 = __fadd_rn(a0, __fmul_rn(v[c + 0], v[c + 0]));
        a1 = __fadd_rn(a1, __fmul_rn(v[c + 1], v[c + 1]));
        a2 = __fadd_rn(a2, __fmul_rn(v[c + 2], v[c + 2]));
        a3 = __fadd_rn(a3, __fmul_rn(v[c + 3], v[c + 3]));
    }
    float sq = __fadd_rn(__fadd_rn(a0, a1), __fadd_rn(a2, a3));
    g_sq[n] = sq;

    // self-dot: sequential FMA chain (GEMM flavor) -> diagonal noise d2 ~ +-eps
    float dot = 0.f;
#pragma unroll
    for (int c = 0; c < CH; ++c) dot = fmaf(v[c], v[c], dot);

    float d2 = fmaf(-2.f, dot, __fadd_rn(sq, sq));
    float f = 0.f;
    if (d2 < 4.f) {
        d2 = fmaxf(d2, 0.f);
        float d = sqrtf(d2);
        f = fmaf(1.5f, d, fmaf(-0.5f, d2, -1.f));
    }

    // int8 quantize: q = clamp(rint(16*x), -127, 127); pack 4 per word
#pragma unroll
    for (int w = 0; w < 8; ++w) {
        uint32_t pk = 0;
#pragma unroll
        for (int b = 0; b < 4; ++b) {
            int q = __float2int_rn(16.f * v[w * 4 + b]);
            q = max(-127, min(127, q));
            pk |= ((uint32_t)q & 0xFFu) << (8 * b);
        }
        s8[tid * 8 + w] = pk;
    }
    __syncthreads();

    // coalesced write-out: 512 words per block
    uint32_t* dst = &g_xq8[blockIdx.x * 64 * 8];
#pragma unroll
    for (int i = tid; i < 512; i += 64) dst[i] = s8[i];

    // deterministic block reduction of diagonal contributions
    red[tid] = f;
    __syncthreads();
#pragma unroll
    for (int s = 32; s > 0; s >>= 1) {
        if (tid < s) red[tid] += red[tid + s];
        __syncthreads();
    }
    if (tid == 0) g_diagpart[blockIdx.x] = red[0];
}

// ---------------------------------------------------------------------------
// mma.sync m16n8k32 s8 (sm_80+ baseline; portable to plain sm_103).
// A row-major (m16 x k32), B col-major (k32 x n8). s32 accumulate (exact).
// ---------------------------------------------------------------------------
__device__ __forceinline__ void imma16832(int* c, const uint32_t* a, const uint32_t* b) {
    asm volatile(
        "mma.sync.aligned.m16n8k32.row.col.s32.s8.s8.s32 "
        "{%0,%1,%2,%3}, {%4,%5,%6,%7}, {%8,%9}, {%0,%1,%2,%3};"
        : "+r"(c[0]), "+r"(c[1]), "+r"(c[2]), "+r"(c[3])
        : "r"(a[0]), "r"(a[1]), "r"(a[2]), "r"(a[3]), "r"(b[0]), "r"(b[1]));
}

// ---------------------------------------------------------------------------
// Cold path: lane-exact fp32 recompute of this lane's 8 rows x 32 cols.
// Runs only when the int8 screen flags (expected ~never off-diagonal).
// ---------------------------------------------------------------------------
__device__ __noinline__ float slow_lane(const float* __restrict__ x,
                                        int I, int J, int m0, int n0,
                                        int qr, int qc) {
    float acc = 0.f;
#pragma unroll 1
    for (int r = 0; r < 8; ++r) {
        int gi = I * TILE + m0 + (r >> 1) * 16 + qr + (r & 1) * 8;
        float si = g_sq[gi];
#pragma unroll 1
        for (int cidx = 0; cidx < 32; ++cidx) {
            int gj = J * TILE + n0 + (cidx >> 1) * 8 + 2 * qc + (cidx & 1);
            if (gi == gj) continue;
            float dt = 0.f;
#pragma unroll
            for (int c = 0; c < CH; ++c)
                dt = fmaf(x[c * NPTS + gi], x[c * NPTS + gj], dt);
            float e2 = fmaf(-2.f, dt, si + g_sq[gj]);
            if (e2 < 4.f) {
                e2 = fmaxf(e2, 0.f);
                float d = sqrtf(e2);
                acc += fmaf(1.5f, d, fmaf(-0.5f, e2, -1.f));
            }
        }
    }
    return acc;
}

// ---------------------------------------------------------------------------
// Kernel B (tile): one CTA per (I,J) 256x256 tile pair, J >= I, 8 warps.
// Warp w owns rows (w&3)*64 .. +63 and cols (w>>2)*128 .. +127.
// int8 IMMA Gram screen: acc initialized to 1024 - rint(128*si); after MMA,
// u = acc - rint(128*sj) > 0  <=>  d2_int8 < 8  (true cut 4, max err ~1.6).
// Off-diagonal: branch-free IADD+IMNMX max-tracking; flag -> exact fp32 lane.
// Diagonal tiles: per-element branch -> exact fp32 (gi==gj excluded).
// ---------------------------------------------------------------------------
__global__ __launch_bounds__(256) void tile_kernel(const float* __restrict__ x) {
    __shared__ __align__(16) uint32_t As[TILE * PQ];   // 12 KB
    __shared__ __align__(16) uint32_t Bs[TILE * PQ];   // 12 KB
    __shared__ int   sqAq[TILE];
    __shared__ int   sqBq[TILE];
    __shared__ float red[256];

    int tid = threadIdx.x;
    int wid = tid >> 5;
    int lane = tid & 31;

    // decode blockIdx -> (I, J) over upper triangle
    int bid = blockIdx.x;
    int I = 0, rem = bid;
    while (rem >= MT - I) { rem -= MT - I; ++I; }
    int J = I + rem;

    // fill A/B tiles: 256 threads, 2 tiles x 256 rows -> 2 rows per thread
    {
        int which = tid >> 7;                  // 0 -> A, 1 -> B
        int r0 = tid & 127;
#pragma unroll
        for (int rr = 0; rr < 2; ++rr) {
            int row  = r0 + rr * 128;
            int base = (which ? J : I) * TILE + row;
            const uint4* src = reinterpret_cast<const uint4*>(&g_xq8[base * 8]);
            uint32_t* dstw = (which ? Bs : As) + row * PQ;
            uint4 w0 = src[0];
            uint4 w1 = src[1];
            *reinterpret_cast<uint4*>(dstw)     = w0;
            *reinterpret_cast<uint4*>(dstw + 4) = w1;
            int sqq = __float2int_rn(128.f * g_sq[base]);
            if (which) sqBq[row] = sqq;
            else       sqAq[row] = sqq;
        }
    }
    __syncthreads();

    int m0 = (wid & 3) * 64;     // row block of this warp (64 rows)
    int n0 = (wid >> 2) * 128;   // col block of this warp (128 cols)
    int qr = lane >> 2;          // 0..7
    int qc = lane & 3;           // 0..3

    // A fragments: afr[mi][4], mi = 0..3 (16-row slabs), K=32 in one frag
    uint32_t afr[4][4];
    int neg_siq[4][2];
#pragma unroll
    for (int mi = 0; mi < 4; ++mi) {
        int r0 = m0 + mi * 16 + qr;
        int r1 = r0 + 8;
        afr[mi][0] = As[r0 * PQ + qc];
        afr[mi][1] = As[r1 * PQ + qc];
        afr[mi][2] = As[r0 * PQ + qc + 4];
        afr[mi][3] = As[r1 * PQ + qc + 4];
        neg_siq[mi][0] = 1024 - sqAq[r0];
        neg_siq[mi][1] = 1024 - sqAq[r1];
    }

    float local = 0.f;

    if (I != J) {
        // ---- hot path: branch-free int screen over 16 n-fragments ----
        int umax = INT_MIN;
#pragma unroll
        for (int nj = 0; nj < 16; ++nj) {
            int jrow = n0 + nj * 8 + qr;
            uint32_t bfr[2];
            bfr[0] = Bs[jrow * PQ + qc];
            bfr[1] = Bs[jrow * PQ + qc + 4];

            int colb = n0 + nj * 8 + 2 * qc;
            int2 sj = *reinterpret_cast<const int2*>(&sqBq[colb]);

#pragma unroll
            for (int mi = 0; mi < 4; ++mi) {
                int acc[4] = {neg_siq[mi][0], neg_siq[mi][0],
                              neg_siq[mi][1], neg_siq[mi][1]};
                imma16832(acc, afr[mi], bfr);
                umax = max(umax, acc[0] - sj.x);
                umax = max(umax, acc[1] - sj.y);
                umax = max(umax, acc[2] - sj.x);
                umax = max(umax, acc[3] - sj.y);
            }
        }
        if (umax > 0)   // conservative screen (true cut 4, int8 err << 4)
            local = slow_lane(x, I, J, m0, n0, qr, qc);
        local *= 2.f;   // symmetry: (I,J) and (J,I) identical
    } else {
        // ---- diagonal tile: per-element exact path on flag ----
#pragma unroll
        for (int nj = 0; nj < 16; ++nj) {
            int jrow = n0 + nj * 8 + qr;
            uint32_t bfr[2];
            bfr[0] = Bs[jrow * PQ + qc];
            bfr[1] = Bs[jrow * PQ + qc + 4];

            int colb = n0 + nj * 8 + 2 * qc;
            int2 sj = *reinterpret_cast<const int2*>(&sqBq[colb]);
            int gj0 = J * TILE + colb;

#pragma unroll
            for (int mi = 0; mi < 4; ++mi) {
                int acc[4] = {neg_siq[mi][0], neg_siq[mi][0],
                              neg_siq[mi][1], neg_siq[mi][1]};
                imma16832(acc, afr[mi], bfr);
#pragma unroll
                for (int e = 0; e < 4; ++e) {
                    int u = acc[e] - ((e & 1) ? sj.y : sj.x);
                    if (u > 0) {
                        int rh = e >> 1;
                        int gi = I * TILE + m0 + mi * 16 + qr + rh * 8;
                        int gj = gj0 + (e & 1);
                        if (gi != gj) {
                            float dt = 0.f;
#pragma unroll
                            for (int c = 0; c < CH; ++c)
                                dt = fmaf(x[c * NPTS + gi], x[c * NPTS + gj], dt);
                            float e2 = fmaf(-2.f, dt, g_sq[gi] + g_sq[gj]);
                            if (e2 < 4.f) {
                                e2 = fmaxf(e2, 0.f);
                                float d = sqrtf(e2);
                                local += fmaf(1.5f, d, fmaf(-0.5f, e2, -1.f));
                            }
                        }
                    }
                }
            }
        }
    }

    // deterministic block reduction
    red[tid] = local;
    __syncthreads();
#pragma unroll
    for (int s = 128; s > 0; s >>= 1) {
        if (tid < s) red[tid] += red[tid + s];
        __syncthreads();
    }
    if (tid == 0) g_partial[bid] = red[0];
}

// ---------------------------------------------------------------------------
// Kernel C: deterministic final reduction; scale by 0.25.
// ---------------------------------------------------------------------------
__global__ void reduce_kernel(float* __restrict__ out) {
    __shared__ float red[256];
    int t = threadIdx.x;
    float s = 0.f;
    for (int i = t; i < NTILES; i += 256) s += g_partial[i];
    for (int i = t; i < NPREP; i += 256) s += g_diagpart[i];
    red[t] = s;
    __syncthreads();
#pragma unroll
    for (int k = 128; k > 0; k >>= 1) {
        if (t < k) red[t] += red[t + k];
        __syncthreads();
    }
    if (t == 0) out[0] = 0.25f * red[0];
}

// ---------------------------------------------------------------------------
extern "C" void kernel_launch(void* const* d_in, const int* in_sizes, int n_in,
                              void* d_out, int out_size) {
    const float* x = (const float*)d_in[0];   // [1, 32, 8192] fp32, channel-major
    float* out = (float*)d_out;

    prep_kernel<<<NPREP, 64>>>(x);
    tile_kernel<<<NTILES, 256>>>(x);
    reduce_kernel<<<1, 256>>>(out);
}